// round 2
// baseline (speedup 1.0000x reference)
#include <cuda_runtime.h>
#include <cuda_bf16.h>
#include <math.h>

// ---------------- problem-size maxima (this dataset instance) ----------------
#define MAXN   50000
#define MAXE   400000
#define MAXET  (MAXE + MAXN)
#define MAXHC  512     // layer1: 4 heads * 128 ch
#define MAXM   256

// ---------------- device scratch (static: no cudaMalloc allowed) -------------
__device__ int   g_src [MAXET];
__device__ int   g_dst [MAXET];
__device__ int   g_srcs[MAXET];          // src ids sorted by dst (CSR payload)
__device__ int   g_cnt [MAXN];
__device__ int   g_rp  [MAXN + 1];
__device__ int   g_cur [MAXN];
__device__ int   g_is64;

__device__ float g_h1 [(size_t)MAXN * MAXHC];  // layer1 pre-agg features
__device__ float g_hp [(size_t)MAXN * MAXHC];  // layer1 output (post PReLU)
__device__ float g_h2 [(size_t)MAXN * MAXM];   // layer2 pre-agg features
__device__ float g_hd [(size_t)MAXN * MAXM];   // decoder pre-agg features
__device__ float g_as1[(size_t)MAXN * 4], g_ad1[(size_t)MAXN * 4];
__device__ float g_as2[MAXN], g_ad2[MAXN];
__device__ float g_asd[MAXN], g_add[MAXN];

// ---------------- graph-building kernels ----------------

// Decide whether edge_index is stored as int64 or int32.
// If int64 (values < 2^31), the high 32-bit word of every element is 0.
__global__ void detect_kernel(const int* __restrict__ ei32, int E) {
    if (threadIdx.x == 0 && blockIdx.x == 0) {
        int nz = 0;
        int cnt = E < 64 ? E : 64;
        for (int i = 0; i < cnt; i++) nz |= ei32[2 * i + 1];
        g_is64 = (nz == 0) ? 1 : 0;
    }
}

__global__ void build_edges(const void* __restrict__ ei, int E, int Nn) {
    int i = blockIdx.x * blockDim.x + threadIdx.x;
    int tot = E + Nn;
    if (i >= tot) return;
    int s, d;
    if (i < E) {
        if (g_is64) {
            const long long* p = (const long long*)ei;
            s = (int)p[i]; d = (int)p[E + i];
        } else {
            const int* p = (const int*)ei;
            s = p[i]; d = p[E + i];
        }
    } else {
        s = d = i - E;   // self loops
    }
    g_src[i] = s; g_dst[i] = d;
}

__global__ void zero_int(int* p, int n) {
    int i = blockIdx.x * blockDim.x + threadIdx.x;
    if (i < n) p[i] = 0;
}

__global__ void hist_kernel(int tot) {
    int i = blockIdx.x * blockDim.x + threadIdx.x;
    if (i < tot) atomicAdd(&g_cnt[g_dst[i]], 1);
}

// single-block inclusive scan of g_cnt -> g_rp[1..N], g_rp[0]=0
__global__ void scan_kernel(int n) {
    __shared__ int sh[1024];
    __shared__ int carry;
    if (threadIdx.x == 0) carry = 0;
    __syncthreads();
    for (int base = 0; base < n; base += 1024) {
        int i = base + threadIdx.x;
        int v = (i < n) ? g_cnt[i] : 0;
        sh[threadIdx.x] = v;
        __syncthreads();
        for (int off = 1; off < 1024; off <<= 1) {
            int t = (threadIdx.x >= off) ? sh[threadIdx.x - off] : 0;
            __syncthreads();
            sh[threadIdx.x] += t;
            __syncthreads();
        }
        if (i < n) g_rp[i + 1] = sh[threadIdx.x] + carry;
        __syncthreads();
        if (threadIdx.x == 0) carry += sh[1023];
        __syncthreads();
    }
    if (threadIdx.x == 0) g_rp[0] = 0;
}

__global__ void copy_cursor(int n) {
    int i = blockIdx.x * blockDim.x + threadIdx.x;
    if (i < n) g_cur[i] = g_rp[i];
}

__global__ void scatter_kernel(int tot) {
    int i = blockIdx.x * blockDim.x + threadIdx.x;
    if (i >= tot) return;
    int d = g_dst[i];
    int pos = atomicAdd(&g_cur[d], 1);
    g_srcs[pos] = g_src[i];
}

// ---------------- SGEMM: C[M,N] = A[M,K] @ B[K,N], row-major -----------------
// BM=128, BN=64, BK=16, 256 threads, thread tile 8x4. Requires N%64==0, K%16==0.
__global__ void __launch_bounds__(256)
sgemm_kernel(const float* __restrict__ A, const float* __restrict__ B,
             float* __restrict__ C, int M, int K, int N) {
    const int BM = 128, BN = 64, BK = 16, TM = 8, TN = 4;
    __shared__ float As[BK][BM];
    __shared__ float Bs[BK][BN];
    int tx = threadIdx.x & 15;       // 0..15  -> N direction
    int ty = threadIdx.x >> 4;       // 0..15  -> M direction
    int tid = threadIdx.x;
    int m0 = blockIdx.y * BM, n0 = blockIdx.x * BN;

    float acc[TM][TN];
#pragma unroll
    for (int i = 0; i < TM; i++)
#pragma unroll
        for (int j = 0; j < TN; j++) acc[i][j] = 0.f;

    for (int k0 = 0; k0 < K; k0 += BK) {
        // load A tile: 128x16 = 512 float4, 2 per thread; transpose into As[k][m]
#pragma unroll
        for (int l = 0; l < 2; l++) {
            int idx = tid + l * 256;            // float4 slot
            int row = idx >> 2;                  // 4 float4 per row
            int kc  = (idx & 3) << 2;
            float4 v = make_float4(0.f, 0.f, 0.f, 0.f);
            int gm = m0 + row;
            if (gm < M) v = *(const float4*)(A + (size_t)gm * K + k0 + kc);
            As[kc + 0][row] = v.x; As[kc + 1][row] = v.y;
            As[kc + 2][row] = v.z; As[kc + 3][row] = v.w;
        }
        // load B tile: 16x64 = 256 float4, 1 per thread
        {
            int row = tid >> 4;                  // 16 float4 per row
            int nc  = (tid & 15) << 2;
            float4 v = *(const float4*)(B + (size_t)(k0 + row) * N + n0 + nc);
            *(float4*)&Bs[row][nc] = v;
        }
        __syncthreads();
#pragma unroll
        for (int kk = 0; kk < BK; kk++) {
            float a[TM], b[TN];
#pragma unroll
            for (int i = 0; i < TM; i++) a[i] = As[kk][ty * TM + i];
#pragma unroll
            for (int j = 0; j < TN; j++) b[j] = Bs[kk][tx * TN + j];
#pragma unroll
            for (int i = 0; i < TM; i++)
#pragma unroll
                for (int j = 0; j < TN; j++) acc[i][j] = fmaf(a[i], b[j], acc[i][j]);
        }
        __syncthreads();
    }
#pragma unroll
    for (int i = 0; i < TM; i++) {
        int gm = m0 + ty * TM + i;
        if (gm >= M) continue;
        float4 v = make_float4(acc[i][0], acc[i][1], acc[i][2], acc[i][3]);
        *(float4*)(C + (size_t)gm * N + n0 + tx * TN) = v;
    }
}

// ---------------- per-node attention logits: alpha_s/alpha_d -----------------
// one warp per (node, head)
__global__ void alpha_kernel(const float* __restrict__ feat,
                             const float* __restrict__ a_src,
                             const float* __restrict__ a_dst,
                             float* __restrict__ as_, float* __restrict__ ad_,
                             int Nn, int H, int C) {
    int warp = (blockIdx.x * blockDim.x + threadIdx.x) >> 5;
    int lane = threadIdx.x & 31;
    if (warp >= Nn * H) return;
    int n = warp / H, h = warp - n * H;
    const float* f = feat + (size_t)n * H * C + h * C;
    const float* s = a_src + h * C;
    const float* d = a_dst + h * C;
    float ss = 0.f, dd = 0.f;
    for (int c = lane; c < C; c += 32) {
        float v = f[c];
        ss = fmaf(v, s[c], ss);
        dd = fmaf(v, d[c], dd);
    }
#pragma unroll
    for (int o = 16; o; o >>= 1) {
        ss += __shfl_down_sync(0xffffffffu, ss, o);
        dd += __shfl_down_sync(0xffffffffu, dd, o);
    }
    if (lane == 0) { as_[warp] = ss; ad_[warp] = dd; }
}

// ---------------- GAT segment-softmax + aggregate (CSR, block per dst) -------
// blockDim.x == H*C. Fuses +bias and optional PReLU.
__global__ void gat_aggregate(const float* __restrict__ feat,   // N x H*C
                              const float* __restrict__ as_,    // N x H
                              const float* __restrict__ ad_,    // N x H
                              const float* __restrict__ bias,   // H*C
                              float* __restrict__ out,          // N x H*C
                              int H, int C, int prelu,
                              const float* __restrict__ prelu_a) {
    int n = blockIdx.x;
    int t = threadIdx.x;
    int HC = H * C;
    int h = t / C;
    extern __shared__ float sh[];   // m[H], denom[H]
    float* sm = sh;
    float* sd = sh + H;
    int s0 = g_rp[n], s1 = g_rp[n + 1];

    if (t < H) {
        float ad = ad_[(size_t)n * H + t];
        float m = -INFINITY;
        for (int k = s0; k < s1; k++) {
            float e = as_[(size_t)g_srcs[k] * H + t] + ad;
            e = e > 0.f ? e : 0.2f * e;
            m = fmaxf(m, e);
        }
        float dsum = 0.f;
        for (int k = s0; k < s1; k++) {
            float e = as_[(size_t)g_srcs[k] * H + t] + ad;
            e = e > 0.f ? e : 0.2f * e;
            dsum += __expf(e - m);
        }
        sm[t] = m;
        sd[t] = dsum + 1e-16f;
    }
    __syncthreads();

    float m  = sm[h];
    float dn = sd[h];
    float ad = ad_[(size_t)n * H + h];
    float acc = 0.f;
    for (int k = s0; k < s1; k++) {
        int s = g_srcs[k];
        float e = as_[(size_t)s * H + h] + ad;
        e = e > 0.f ? e : 0.2f * e;
        float w = __expf(e - m) / dn;
        acc = fmaf(feat[(size_t)s * HC + t], w, acc);
    }
    float v = acc + bias[t];
    if (prelu) { float a = prelu_a[0]; v = v >= 0.f ? v : a * v; }
    out[(size_t)n * HC + t] = v;
}

// ---------------- host orchestration ----------------
static inline int ceil_div(int a, int b) { return (a + b - 1) / b; }

extern "C" void kernel_launch(void* const* d_in, const int* in_sizes, int n_in,
                              void* d_out, int out_size) {
    const float* x       = (const float*)d_in[0];
    const void*  eidx    = d_in[1];
    const float* W1      = (const float*)d_in[2];
    const float* a_src1  = (const float*)d_in[3];
    const float* a_dst1  = (const float*)d_in[4];
    const float* b1      = (const float*)d_in[5];
    const float* prelu_a = (const float*)d_in[6];
    const float* W2      = (const float*)d_in[7];
    const float* a_src2  = (const float*)d_in[8];
    const float* a_dst2  = (const float*)d_in[9];
    const float* b2      = (const float*)d_in[10];
    const float* Wd      = (const float*)d_in[11];
    const float* a_srcd  = (const float*)d_in[12];
    const float* a_dstd  = (const float*)d_in[13];
    const float* bd      = (const float*)d_in[14];

    // derive dims from sizes
    const int HHc = in_sizes[3];          // H * Hc = 512
    const int H1  = 4;
    const int C1  = HHc / H1;             // 128
    const int M   = in_sizes[8];          // 256
    const int D   = in_sizes[12];         // 256
    const int N   = in_sizes[0] / D;      // 50000
    const int E   = in_sizes[1] / 2;      // 400000
    const int ET  = E + N;

    float* out   = (float*)d_out;
    float* z     = out;                    // N x M
    float* x_hat = out + (size_t)N * M;    // N x D

    // device-global pointers (host side)
    float *h1, *hp, *h2, *hd;
    float *as1, *ad1, *as2, *ad2, *asd, *add;
    int *cnt_p;
    cudaGetSymbolAddress((void**)&h1,  g_h1);
    cudaGetSymbolAddress((void**)&hp,  g_hp);
    cudaGetSymbolAddress((void**)&h2,  g_h2);
    cudaGetSymbolAddress((void**)&hd,  g_hd);
    cudaGetSymbolAddress((void**)&as1, g_as1);
    cudaGetSymbolAddress((void**)&ad1, g_ad1);
    cudaGetSymbolAddress((void**)&as2, g_as2);
    cudaGetSymbolAddress((void**)&ad2, g_ad2);
    cudaGetSymbolAddress((void**)&asd, g_asd);
    cudaGetSymbolAddress((void**)&add, g_add);
    cudaGetSymbolAddress((void**)&cnt_p, g_cnt);

    // ---- build CSR by destination (includes self-loops) ----
    detect_kernel<<<1, 32>>>((const int*)eidx, E);
    build_edges<<<ceil_div(ET, 256), 256>>>(eidx, E, N);
    zero_int<<<ceil_div(N, 256), 256>>>(cnt_p, N);
    hist_kernel<<<ceil_div(ET, 256), 256>>>(ET);
    scan_kernel<<<1, 1024>>>(N);
    copy_cursor<<<ceil_div(N, 256), 256>>>(N);
    scatter_kernel<<<ceil_div(ET, 256), 256>>>(ET);

    dim3 blk(256);
    // ---- layer 1: x[N,D] @ W1[D,HHc] -> h1; alpha; aggregate (+b1, PReLU) ----
    {
        dim3 grid(HHc / 64, ceil_div(N, 128));
        sgemm_kernel<<<grid, blk>>>(x, W1, h1, N, D, HHc);
        int warps = N * H1;
        alpha_kernel<<<ceil_div(warps * 32, 256), 256>>>(h1, a_src1, a_dst1, as1, ad1, N, H1, C1);
        gat_aggregate<<<N, HHc, 2 * H1 * sizeof(float)>>>(h1, as1, ad1, b1, hp, H1, C1, 1, prelu_a);
    }
    // ---- layer 2: hp[N,HHc] @ W2[HHc,M] -> h2; alpha; aggregate -> z (+b2) ----
    {
        dim3 grid(M / 64, ceil_div(N, 128));
        sgemm_kernel<<<grid, blk>>>(hp, W2, h2, N, HHc, M);
        alpha_kernel<<<ceil_div(N * 32, 256), 256>>>(h2, a_src2, a_dst2, as2, ad2, N, 1, M);
        gat_aggregate<<<N, M, 2 * sizeof(float)>>>(h2, as2, ad2, b2, z, 1, M, 0, prelu_a);
    }
    // ---- decoder: z[N,M] @ Wd[M,D] -> hd; alpha; aggregate -> x_hat (+bd) ----
    {
        dim3 grid(D / 64, ceil_div(N, 128));
        sgemm_kernel<<<grid, blk>>>(z, Wd, hd, N, M, D);
        alpha_kernel<<<ceil_div(N * 32, 256), 256>>>(hd, a_srcd, a_dstd, asd, add, N, 1, D);
        gat_aggregate<<<N, D, 2 * sizeof(float)>>>(hd, asd, add, bd, x_hat, 1, D, 0, prelu_a);
    }
}

// round 3
// speedup vs baseline: 1.1708x; 1.1708x over previous
#include <cuda_runtime.h>
#include <cuda_bf16.h>
#include <math.h>

// ---------------- problem-size maxima (this dataset instance) ----------------
#define MAXN   50000
#define MAXE   400000
#define MAXET  (MAXE + MAXN)
#define MAXHC  512
#define MAXM   256

typedef unsigned long long ULL;

// ---------------- device scratch (static: no cudaMalloc allowed) -------------
__device__ int   g_src [MAXET];
__device__ int   g_dst [MAXET];
__device__ int   g_srcs[MAXET];
__device__ int   g_cnt [MAXN];
__device__ int   g_rp  [MAXN + 1];
__device__ int   g_cur [MAXN];
__device__ int   g_is64;

__device__ float g_h1 [(size_t)MAXN * MAXHC];
__device__ float g_hp [(size_t)MAXN * MAXHC];
__device__ float g_h2 [(size_t)MAXN * MAXM];
__device__ float g_hd [(size_t)MAXN * MAXM];
__device__ float g_as1[(size_t)MAXN * 4], g_ad1[(size_t)MAXN * 4];
__device__ float g_as2[MAXN], g_ad2[MAXN];
__device__ float g_asd[MAXN], g_add[MAXN];

// ---------------- graph-building kernels ----------------
__global__ void detect_kernel(const int* __restrict__ ei32, int E) {
    if (threadIdx.x == 0 && blockIdx.x == 0) {
        int nz = 0;
        int cnt = E < 64 ? E : 64;
        for (int i = 0; i < cnt; i++) nz |= ei32[2 * i + 1];
        g_is64 = (nz == 0) ? 1 : 0;
    }
}

__global__ void build_edges(const void* __restrict__ ei, int E, int Nn) {
    int i = blockIdx.x * blockDim.x + threadIdx.x;
    int tot = E + Nn;
    if (i >= tot) return;
    int s, d;
    if (i < E) {
        if (g_is64) {
            const long long* p = (const long long*)ei;
            s = (int)p[i]; d = (int)p[E + i];
        } else {
            const int* p = (const int*)ei;
            s = p[i]; d = p[E + i];
        }
    } else {
        s = d = i - E;
    }
    g_src[i] = s; g_dst[i] = d;
}

__global__ void zero_int(int* p, int n) {
    int i = blockIdx.x * blockDim.x + threadIdx.x;
    if (i < n) p[i] = 0;
}

__global__ void hist_kernel(int tot) {
    int i = blockIdx.x * blockDim.x + threadIdx.x;
    if (i < tot) atomicAdd(&g_cnt[g_dst[i]], 1);
}

__global__ void scan_kernel(int n) {
    __shared__ int sh[1024];
    __shared__ int carry;
    if (threadIdx.x == 0) carry = 0;
    __syncthreads();
    for (int base = 0; base < n; base += 1024) {
        int i = base + threadIdx.x;
        int v = (i < n) ? g_cnt[i] : 0;
        sh[threadIdx.x] = v;
        __syncthreads();
        for (int off = 1; off < 1024; off <<= 1) {
            int t = (threadIdx.x >= off) ? sh[threadIdx.x - off] : 0;
            __syncthreads();
            sh[threadIdx.x] += t;
            __syncthreads();
        }
        if (i < n) g_rp[i + 1] = sh[threadIdx.x] + carry;
        __syncthreads();
        if (threadIdx.x == 0) carry += sh[1023];
        __syncthreads();
    }
    if (threadIdx.x == 0) g_rp[0] = 0;
}

__global__ void copy_cursor(int n) {
    int i = blockIdx.x * blockDim.x + threadIdx.x;
    if (i < n) g_cur[i] = g_rp[i];
}

__global__ void scatter_kernel(int tot) {
    int i = blockIdx.x * blockDim.x + threadIdx.x;
    if (i >= tot) return;
    int d = g_dst[i];
    int pos = atomicAdd(&g_cur[d], 1);
    g_srcs[pos] = g_src[i];
}

// ---------------- f32x2 packed-FMA SGEMM ----------------
// C[M,N] = A[M,K] @ B[K,N], row-major. BM=BN=128, BK=16, 256 thr, 8x8/thread.
// Requires N%128==0, K%16==0. M guarded.
__device__ __forceinline__ ULL pack2(float lo, float hi) {
    ULL r; asm("mov.b64 %0, {%1, %2};" : "=l"(r) : "f"(lo), "f"(hi)); return r;
}
__device__ __forceinline__ void fma2(ULL& d, ULL a, ULL b) {
    asm("fma.rn.f32x2 %0, %1, %2, %0;" : "+l"(d) : "l"(a), "l"(b));
}

__global__ void __launch_bounds__(256, 2)
sgemm128(const float* __restrict__ A, const float* __restrict__ B,
         float* __restrict__ C, int M, int K, int N) {
    const int BM = 128, BN = 128, BK = 16;
    __shared__ float As[2][BK][BM];   // transposed: As[k][m]
    __shared__ float Bs[2][BK][BN];
    int tid = threadIdx.x;
    int tx = tid & 15;          // N dir
    int ty = tid >> 4;          // M dir
    int m0 = blockIdx.y * BM, n0 = blockIdx.x * BN;

    // A tile: 128x16 = 512 float4, 2/thread
    int aRow = tid >> 2;                // 0..63 (+64)
    int aKc  = (tid & 3) << 2;
    // B tile: 16x128 = 512 float4, 2/thread
    int bRow = tid >> 5;                // 0..7 (+8)
    int bCol = (tid & 31) << 2;

    ULL acc[8][4];
#pragma unroll
    for (int i = 0; i < 8; i++)
#pragma unroll
        for (int j = 0; j < 4; j++) acc[i][j] = 0ULL;

    float4 pa0, pa1, pb0, pb1;
    const float4 zf4 = make_float4(0.f, 0.f, 0.f, 0.f);

    // load tile 0
    {
        int gm0 = m0 + aRow, gm1 = m0 + aRow + 64;
        pa0 = (gm0 < M) ? *(const float4*)(A + (size_t)gm0 * K + aKc) : zf4;
        pa1 = (gm1 < M) ? *(const float4*)(A + (size_t)gm1 * K + aKc) : zf4;
        pb0 = *(const float4*)(B + (size_t)(bRow)     * N + n0 + bCol);
        pb1 = *(const float4*)(B + (size_t)(bRow + 8) * N + n0 + bCol);
    }
    int buf = 0;
    {
        As[0][aKc + 0][aRow] = pa0.x; As[0][aKc + 1][aRow] = pa0.y;
        As[0][aKc + 2][aRow] = pa0.z; As[0][aKc + 3][aRow] = pa0.w;
        As[0][aKc + 0][aRow + 64] = pa1.x; As[0][aKc + 1][aRow + 64] = pa1.y;
        As[0][aKc + 2][aRow + 64] = pa1.z; As[0][aKc + 3][aRow + 64] = pa1.w;
        *(float4*)&Bs[0][bRow][bCol]     = pb0;
        *(float4*)&Bs[0][bRow + 8][bCol] = pb1;
    }
    __syncthreads();

    int nt = K / BK;
    for (int t = 0; t < nt; t++) {
        if (t + 1 < nt) {
            int k0 = (t + 1) * BK;
            int gm0 = m0 + aRow, gm1 = m0 + aRow + 64;
            pa0 = (gm0 < M) ? *(const float4*)(A + (size_t)gm0 * K + k0 + aKc) : zf4;
            pa1 = (gm1 < M) ? *(const float4*)(A + (size_t)gm1 * K + k0 + aKc) : zf4;
            pb0 = *(const float4*)(B + (size_t)(k0 + bRow)     * N + n0 + bCol);
            pb1 = *(const float4*)(B + (size_t)(k0 + bRow + 8) * N + n0 + bCol);
        }
#pragma unroll
        for (int kk = 0; kk < BK; kk++) {
            float4 a0 = *(float4*)&As[buf][kk][ty * 8];
            float4 a1 = *(float4*)&As[buf][kk][ty * 8 + 4];
            float4 b0 = *(float4*)&Bs[buf][kk][tx * 8];
            float4 b1 = *(float4*)&Bs[buf][kk][tx * 8 + 4];
            ULL bb[4];
            bb[0] = pack2(b0.x, b0.y); bb[1] = pack2(b0.z, b0.w);
            bb[2] = pack2(b1.x, b1.y); bb[3] = pack2(b1.z, b1.w);
            float av[8] = {a0.x, a0.y, a0.z, a0.w, a1.x, a1.y, a1.z, a1.w};
#pragma unroll
            for (int i = 0; i < 8; i++) {
                ULL ai = pack2(av[i], av[i]);
                fma2(acc[i][0], ai, bb[0]);
                fma2(acc[i][1], ai, bb[1]);
                fma2(acc[i][2], ai, bb[2]);
                fma2(acc[i][3], ai, bb[3]);
            }
        }
        if (t + 1 < nt) {
            int nb = buf ^ 1;
            As[nb][aKc + 0][aRow] = pa0.x; As[nb][aKc + 1][aRow] = pa0.y;
            As[nb][aKc + 2][aRow] = pa0.z; As[nb][aKc + 3][aRow] = pa0.w;
            As[nb][aKc + 0][aRow + 64] = pa1.x; As[nb][aKc + 1][aRow + 64] = pa1.y;
            As[nb][aKc + 2][aRow + 64] = pa1.z; As[nb][aKc + 3][aRow + 64] = pa1.w;
            *(float4*)&Bs[nb][bRow][bCol]     = pb0;
            *(float4*)&Bs[nb][bRow + 8][bCol] = pb1;
            __syncthreads();
            buf = nb;
        }
    }

#pragma unroll
    for (int i = 0; i < 8; i++) {
        int gm = m0 + ty * 8 + i;
        if (gm >= M) continue;
        union { ULL u[2]; float4 f; } c0, c1;
        c0.u[0] = acc[i][0]; c0.u[1] = acc[i][1];
        c1.u[0] = acc[i][2]; c1.u[1] = acc[i][3];
        float* cp = C + (size_t)gm * N + n0 + tx * 8;
        *(float4*)cp       = c0.f;
        *(float4*)(cp + 4) = c1.f;
    }
}

// ---------------- per-node attention logits ----------------
__global__ void alpha_kernel(const float* __restrict__ feat,
                             const float* __restrict__ a_src,
                             const float* __restrict__ a_dst,
                             float* __restrict__ as_, float* __restrict__ ad_,
                             int Nn, int H, int C) {
    int warp = (blockIdx.x * blockDim.x + threadIdx.x) >> 5;
    int lane = threadIdx.x & 31;
    if (warp >= Nn * H) return;
    int n = warp / H, h = warp - n * H;
    const float* f = feat + (size_t)n * H * C + h * C;
    const float* s = a_src + h * C;
    const float* d = a_dst + h * C;
    float ss = 0.f, dd = 0.f;
    for (int c = lane; c < C; c += 32) {
        float v = f[c];
        ss = fmaf(v, s[c], ss);
        dd = fmaf(v, d[c], dd);
    }
#pragma unroll
    for (int o = 16; o; o >>= 1) {
        ss += __shfl_down_sync(0xffffffffu, ss, o);
        dd += __shfl_down_sync(0xffffffffu, dd, o);
    }
    if (lane == 0) { as_[warp] = ss; ad_[warp] = dd; }
}

// ---------------- GAT segment-softmax + aggregate ----------------
// block per dst node; blockDim = H*C. Warp-parallel softmax stats.
__global__ void gat_aggregate(const float* __restrict__ feat,
                              const float* __restrict__ as_,
                              const float* __restrict__ ad_,
                              const float* __restrict__ bias,
                              float* __restrict__ out,
                              int H, int C, int prelu,
                              const float* __restrict__ prelu_a) {
    int n = blockIdx.x;
    int t = threadIdx.x;
    int HC = H * C;
    int h = t / C;
    extern __shared__ float sh[];
    float* sm = sh;
    float* sd = sh + H;
    int s0 = g_rp[n], s1 = g_rp[n + 1];

    int warp = t >> 5, lane = t & 31;
    if (warp < H) {
        float ad = ad_[(size_t)n * H + warp];
        float m = -INFINITY;
        for (int k = s0 + lane; k < s1; k += 32) {
            float e = as_[(size_t)g_srcs[k] * H + warp] + ad;
            e = e > 0.f ? e : 0.2f * e;
            m = fmaxf(m, e);
        }
#pragma unroll
        for (int o = 16; o; o >>= 1) m = fmaxf(m, __shfl_xor_sync(0xffffffffu, m, o));
        float dsum = 0.f;
        for (int k = s0 + lane; k < s1; k += 32) {
            float e = as_[(size_t)g_srcs[k] * H + warp] + ad;
            e = e > 0.f ? e : 0.2f * e;
            dsum += __expf(e - m);
        }
#pragma unroll
        for (int o = 16; o; o >>= 1) dsum += __shfl_xor_sync(0xffffffffu, dsum, o);
        if (lane == 0) { sm[warp] = m; sd[warp] = dsum + 1e-16f; }
    }
    __syncthreads();

    float m  = sm[h];
    float dn = sd[h];
    float ad = ad_[(size_t)n * H + h];
    float acc = 0.f;
    for (int k = s0; k < s1; k++) {
        int s = g_srcs[k];
        float e = as_[(size_t)s * H + h] + ad;
        e = e > 0.f ? e : 0.2f * e;
        float w = __expf(e - m) / dn;
        acc = fmaf(feat[(size_t)s * HC + t], w, acc);
    }
    float v = acc + bias[t];
    if (prelu) { float a = prelu_a[0]; v = v >= 0.f ? v : a * v; }
    out[(size_t)n * HC + t] = v;
}

// ---------------- host orchestration ----------------
static inline int ceil_div(int a, int b) { return (a + b - 1) / b; }

extern "C" void kernel_launch(void* const* d_in, const int* in_sizes, int n_in,
                              void* d_out, int out_size) {
    const float* x       = (const float*)d_in[0];
    const void*  eidx    = d_in[1];
    const float* W1      = (const float*)d_in[2];
    const float* a_src1  = (const float*)d_in[3];
    const float* a_dst1  = (const float*)d_in[4];
    const float* b1      = (const float*)d_in[5];
    const float* prelu_a = (const float*)d_in[6];
    const float* W2      = (const float*)d_in[7];
    const float* a_src2  = (const float*)d_in[8];
    const float* a_dst2  = (const float*)d_in[9];
    const float* b2      = (const float*)d_in[10];
    const float* Wd      = (const float*)d_in[11];
    const float* a_srcd  = (const float*)d_in[12];
    const float* a_dstd  = (const float*)d_in[13];
    const float* bd      = (const float*)d_in[14];

    const int HHc = in_sizes[3];
    const int H1  = 4;
    const int C1  = HHc / H1;
    const int M   = in_sizes[8];
    const int D   = in_sizes[12];
    const int N   = in_sizes[0] / D;
    const int E   = in_sizes[1] / 2;
    const int ET  = E + N;

    float* out   = (float*)d_out;
    float* z     = out;
    float* x_hat = out + (size_t)N * M;

    float *h1, *hp, *h2, *hd;
    float *as1, *ad1, *as2, *ad2, *asd, *add;
    int *cnt_p;
    cudaGetSymbolAddress((void**)&h1,  g_h1);
    cudaGetSymbolAddress((void**)&hp,  g_hp);
    cudaGetSymbolAddress((void**)&h2,  g_h2);
    cudaGetSymbolAddress((void**)&hd,  g_hd);
    cudaGetSymbolAddress((void**)&as1, g_as1);
    cudaGetSymbolAddress((void**)&ad1, g_ad1);
    cudaGetSymbolAddress((void**)&as2, g_as2);
    cudaGetSymbolAddress((void**)&ad2, g_ad2);
    cudaGetSymbolAddress((void**)&asd, g_asd);
    cudaGetSymbolAddress((void**)&add, g_add);
    cudaGetSymbolAddress((void**)&cnt_p, g_cnt);

    detect_kernel<<<1, 32>>>((const int*)eidx, E);
    build_edges<<<ceil_div(ET, 256), 256>>>(eidx, E, N);
    zero_int<<<ceil_div(N, 256), 256>>>(cnt_p, N);
    hist_kernel<<<ceil_div(ET, 256), 256>>>(ET);
    scan_kernel<<<1, 1024>>>(N);
    copy_cursor<<<ceil_div(N, 256), 256>>>(N);
    scatter_kernel<<<ceil_div(ET, 256), 256>>>(ET);

    dim3 blk(256);
    // layer 1
    {
        dim3 grid(HHc / 128, ceil_div(N, 128));
        sgemm128<<<grid, blk>>>(x, W1, h1, N, D, HHc);
        int warps = N * H1;
        alpha_kernel<<<ceil_div(warps * 32, 256), 256>>>(h1, a_src1, a_dst1, as1, ad1, N, H1, C1);
        gat_aggregate<<<N, HHc, 2 * H1 * sizeof(float)>>>(h1, as1, ad1, b1, hp, H1, C1, 1, prelu_a);
    }
    // layer 2
    {
        dim3 grid(M / 128, ceil_div(N, 128));
        sgemm128<<<grid, blk>>>(hp, W2, h2, N, HHc, M);
        alpha_kernel<<<ceil_div(N * 32, 256), 256>>>(h2, a_src2, a_dst2, as2, ad2, N, 1, M);
        gat_aggregate<<<N, M, 2 * sizeof(float)>>>(h2, as2, ad2, b2, z, 1, M, 0, prelu_a);
    }
    // decoder
    {
        dim3 grid(D / 128, ceil_div(N, 128));
        sgemm128<<<grid, blk>>>(z, Wd, hd, N, M, D);
        alpha_kernel<<<ceil_div(N * 32, 256), 256>>>(hd, a_srcd, a_dstd, asd, add, N, 1, D);
        gat_aggregate<<<N, D, 2 * sizeof(float)>>>(hd, asd, add, bd, x_hat, 1, D, 0, prelu_a);
    }
}

// round 5
// speedup vs baseline: 1.2402x; 1.0592x over previous
#include <cuda_runtime.h>
#include <cuda_bf16.h>
#include <math.h>
#include <stdint.h>

// ---------------- problem-size maxima ----------------
#define MAXN   50000
#define MAXE   400000
#define MAXET  (MAXE + MAXN)
#define MAXHC  512
#define MAXM   256

// ---------------- device scratch ----------------
__device__ int   g_src [MAXET];
__device__ int   g_dst [MAXET];
__device__ int   g_srcs[MAXET];
__device__ int   g_cnt [MAXN];
__device__ int   g_rp  [MAXN + 1];
__device__ int   g_cur [MAXN];
__device__ int   g_is64;

__device__ float g_h1 [(size_t)MAXN * MAXHC];   // GEMM outputs (fp32)
__device__ float g_h2 [(size_t)MAXN * MAXM];
__device__ float g_hd [(size_t)MAXN * MAXM];
__device__ __nv_bfloat16 g_ahi[(size_t)MAXN * MAXHC];  // split A operand
__device__ __nv_bfloat16 g_alo[(size_t)MAXN * MAXHC];
__device__ __nv_bfloat16 g_wthi[512 * 512];            // split W^T operand
__device__ __nv_bfloat16 g_wtlo[512 * 512];
__device__ float g_as1[(size_t)MAXN * 4], g_ad1[(size_t)MAXN * 4];
__device__ float g_as2[MAXN], g_ad2[MAXN];
__device__ float g_asd[MAXN], g_add[MAXN];

// ---------------- PTX helpers ----------------
__device__ __forceinline__ uint32_t smem_u32(const void* p) {
    uint32_t a;
    asm("{ .reg .u64 t; cvta.to.shared.u64 t, %1; cvt.u32.u64 %0, t; }" : "=r"(a) : "l"(p));
    return a;
}
__device__ __forceinline__ void ldmx4(uint32_t* r, uint32_t addr) {
    asm volatile("ldmatrix.sync.aligned.m8n8.x4.shared.b16 {%0,%1,%2,%3}, [%4];"
        : "=r"(r[0]), "=r"(r[1]), "=r"(r[2]), "=r"(r[3]) : "r"(addr));
}
__device__ __forceinline__ void mma16816(float* c, const uint32_t* a,
                                         uint32_t b0, uint32_t b1) {
    asm volatile(
        "mma.sync.aligned.m16n8k16.row.col.f32.bf16.bf16.f32 "
        "{%0,%1,%2,%3}, {%4,%5,%6,%7}, {%8,%9}, {%0,%1,%2,%3};"
        : "+f"(c[0]), "+f"(c[1]), "+f"(c[2]), "+f"(c[3])
        : "r"(a[0]), "r"(a[1]), "r"(a[2]), "r"(a[3]), "r"(b0), "r"(b1));
}

// ---------------- graph-building kernels ----------------
__global__ void detect_kernel(const int* __restrict__ ei32, int E) {
    if (threadIdx.x == 0 && blockIdx.x == 0) {
        int nz = 0;
        int cnt = E < 64 ? E : 64;
        for (int i = 0; i < cnt; i++) nz |= ei32[2 * i + 1];
        g_is64 = (nz == 0) ? 1 : 0;
    }
}
__global__ void build_edges(const void* __restrict__ ei, int E, int Nn) {
    int i = blockIdx.x * blockDim.x + threadIdx.x;
    int tot = E + Nn;
    if (i >= tot) return;
    int s, d;
    if (i < E) {
        if (g_is64) {
            const long long* p = (const long long*)ei;
            s = (int)p[i]; d = (int)p[E + i];
        } else {
            const int* p = (const int*)ei;
            s = p[i]; d = p[E + i];
        }
    } else { s = d = i - E; }
    g_src[i] = s; g_dst[i] = d;
}
__global__ void zero_int(int* p, int n) {
    int i = blockIdx.x * blockDim.x + threadIdx.x;
    if (i < n) p[i] = 0;
}
__global__ void hist_kernel(int tot) {
    int i = blockIdx.x * blockDim.x + threadIdx.x;
    if (i < tot) atomicAdd(&g_cnt[g_dst[i]], 1);
}
__global__ void scan_kernel(int n) {
    __shared__ int sh[1024];
    __shared__ int carry;
    if (threadIdx.x == 0) carry = 0;
    __syncthreads();
    for (int base = 0; base < n; base += 1024) {
        int i = base + threadIdx.x;
        int v = (i < n) ? g_cnt[i] : 0;
        sh[threadIdx.x] = v;
        __syncthreads();
        for (int off = 1; off < 1024; off <<= 1) {
            int t = (threadIdx.x >= off) ? sh[threadIdx.x - off] : 0;
            __syncthreads();
            sh[threadIdx.x] += t;
            __syncthreads();
        }
        if (i < n) g_rp[i + 1] = sh[threadIdx.x] + carry;
        __syncthreads();
        if (threadIdx.x == 0) carry += sh[1023];
        __syncthreads();
    }
    if (threadIdx.x == 0) g_rp[0] = 0;
}
__global__ void copy_cursor(int n) {
    int i = blockIdx.x * blockDim.x + threadIdx.x;
    if (i < n) g_cur[i] = g_rp[i];
}
__global__ void scatter_kernel(int tot) {
    int i = blockIdx.x * blockDim.x + threadIdx.x;
    if (i >= tot) return;
    int d = g_dst[i];
    int pos = atomicAdd(&g_cur[d], 1);
    g_srcs[pos] = g_src[i];
}

// ---------------- bf16 split conversions ----------------
__global__ void split_kernel(const float* __restrict__ src,
                             __nv_bfloat16* __restrict__ hi,
                             __nv_bfloat16* __restrict__ lo, int total) {
    int i = blockIdx.x * blockDim.x + threadIdx.x;
    if (i >= total) return;
    float v = src[i];
    __nv_bfloat16 h = __float2bfloat16(v);
    hi[i] = h;
    lo[i] = __float2bfloat16(v - __bfloat162float(h));
}
// W[K,N] -> Wt_hi/lo[N,K]
__global__ void wtsplit_kernel(const float* __restrict__ W,
                               __nv_bfloat16* __restrict__ hi,
                               __nv_bfloat16* __restrict__ lo, int K, int N) {
    int idx = blockIdx.x * blockDim.x + threadIdx.x;
    if (idx >= K * N) return;
    int k = idx / N, n = idx - k * N;
    float v = W[idx];
    __nv_bfloat16 h = __float2bfloat16(v);
    hi[(size_t)n * K + k] = h;
    lo[(size_t)n * K + k] = __float2bfloat16(v - __bfloat162float(h));
}

// ---------------- split-bf16 tensor-core GEMM (mma.sync / HMMA) --------------
// C[M,N] = Ahi/lo[M,K] @ (Bt hi/lo[N,K])^T, fp32 accumulate.
// CTA tile 128x64, BK=32, 8 warps (4M x 2N), warp tile 32x32.
// Requires K%32==0, N%64==0. M guarded.
__global__ void __launch_bounds__(256, 2)
mma_gemm(const __nv_bfloat16* __restrict__ Ahi, const __nv_bfloat16* __restrict__ Alo,
         const __nv_bfloat16* __restrict__ Bhi, const __nv_bfloat16* __restrict__ Blo,
         float* __restrict__ C, int M, int K, int N) {
    // 80-byte row stride: ldmatrix bank-conflict-free (r*20 mod 32 all distinct)
    __shared__ __align__(16) uint8_t sAh[128 * 80], sAl[128 * 80];
    __shared__ __align__(16) uint8_t sBh[64 * 80],  sBl[64 * 80];
    int tid = threadIdx.x, lane = tid & 31, wid = tid >> 5;
    int wm = wid & 3, wn = wid >> 2;
    int m0 = blockIdx.y * 128, n0 = blockIdx.x * 64;

    // global load mapping: 4 uint4 per 32-col row
    int lr = tid >> 2, lc = tid & 3;
    int gm0 = m0 + lr, gm1 = m0 + lr + 64;
    const size_t a0off = (size_t)gm0 * K + lc * 8;
    const size_t a1off = (size_t)gm1 * K + lc * 8;
    const size_t bOff  = (size_t)(n0 + lr) * K + lc * 8;
    uint32_t stA0 = (uint32_t)(lr * 80 + lc * 16);
    uint32_t stA1 = (uint32_t)((lr + 64) * 80 + lc * 16);

    uint32_t sAhB = smem_u32(sAh), sAlB = smem_u32(sAl);
    uint32_t sBhB = smem_u32(sBh), sBlB = smem_u32(sBl);

    // ldmatrix per-lane offsets
    uint32_t aoffs[2], boffs[2];
#pragma unroll
    for (int mt = 0; mt < 2; mt++)
        aoffs[mt] = (uint32_t)((wm * 32 + mt * 16 + (lane & 15)) * 80 + (lane >> 4) * 16);
#pragma unroll
    for (int p = 0; p < 2; p++)
        boffs[p] = (uint32_t)((wn * 32 + p * 16 + ((lane >> 3) & 1) * 8 + (lane & 7)) * 80
                              + (lane >> 4) * 16);

    float acc[2][4][4];
#pragma unroll
    for (int i = 0; i < 2; i++)
#pragma unroll
        for (int j = 0; j < 4; j++)
#pragma unroll
            for (int q = 0; q < 4; q++) acc[i][j][q] = 0.f;

    const uint4 z4 = make_uint4(0, 0, 0, 0);
    uint4 pa0h, pa1h, pa0l, pa1l, pbh, pbl;
    // fetch chunk 0
    pa0h = (gm0 < M) ? *(const uint4*)(Ahi + a0off) : z4;
    pa1h = (gm1 < M) ? *(const uint4*)(Ahi + a1off) : z4;
    pa0l = (gm0 < M) ? *(const uint4*)(Alo + a0off) : z4;
    pa1l = (gm1 < M) ? *(const uint4*)(Alo + a1off) : z4;
    pbh  = *(const uint4*)(Bhi + bOff);
    pbl  = *(const uint4*)(Blo + bOff);

    int nch = K >> 5;
    for (int ch = 0; ch < nch; ch++) {
        *(uint4*)(sAh + stA0) = pa0h;
        *(uint4*)(sAh + stA1) = pa1h;
        *(uint4*)(sAl + stA0) = pa0l;
        *(uint4*)(sAl + stA1) = pa1l;
        *(uint4*)(sBh + stA0) = pbh;
        *(uint4*)(sBl + stA0) = pbl;
        __syncthreads();

        if (ch + 1 < nch) {
            int k8 = (ch + 1) * 32;
            pa0h = (gm0 < M) ? *(const uint4*)(Ahi + a0off + k8) : z4;
            pa1h = (gm1 < M) ? *(const uint4*)(Ahi + a1off + k8) : z4;
            pa0l = (gm0 < M) ? *(const uint4*)(Alo + a0off + k8) : z4;
            pa1l = (gm1 < M) ? *(const uint4*)(Alo + a1off + k8) : z4;
            pbh  = *(const uint4*)(Bhi + bOff + k8);
            pbl  = *(const uint4*)(Blo + bOff + k8);
        }

#pragma unroll
        for (int ks = 0; ks < 2; ks++) {
            uint32_t AH[2][4], AL[2][4], BH[2][4], BL[2][4];
            ldmx4(AH[0], sAhB + aoffs[0] + ks * 32);
            ldmx4(AH[1], sAhB + aoffs[1] + ks * 32);
            ldmx4(AL[0], sAlB + aoffs[0] + ks * 32);
            ldmx4(AL[1], sAlB + aoffs[1] + ks * 32);
            ldmx4(BH[0], sBhB + boffs[0] + ks * 32);
            ldmx4(BH[1], sBhB + boffs[1] + ks * 32);
            ldmx4(BL[0], sBlB + boffs[0] + ks * 32);
            ldmx4(BL[1], sBlB + boffs[1] + ks * 32);
#pragma unroll
            for (int mt = 0; mt < 2; mt++) {
#pragma unroll
                for (int p = 0; p < 2; p++) {
                    // nt = p*2+0 uses regs {0,2}; nt = p*2+1 uses {1,3}
                    mma16816(acc[mt][p * 2 + 0], AH[mt], BH[p][0], BH[p][2]);
                    mma16816(acc[mt][p * 2 + 1], AH[mt], BH[p][1], BH[p][3]);
                    mma16816(acc[mt][p * 2 + 0], AH[mt], BL[p][0], BL[p][2]);
                    mma16816(acc[mt][p * 2 + 1], AH[mt], BL[p][1], BL[p][3]);
                    mma16816(acc[mt][p * 2 + 0], AL[mt], BH[p][0], BH[p][2]);
                    mma16816(acc[mt][p * 2 + 1], AL[mt], BH[p][1], BH[p][3]);
                }
            }
        }
        __syncthreads();
    }

    // epilogue
#pragma unroll
    for (int mt = 0; mt < 2; mt++) {
        int gr0 = m0 + wm * 32 + mt * 16 + (lane >> 2);
        int gr1 = gr0 + 8;
#pragma unroll
        for (int nt = 0; nt < 4; nt++) {
            int gc = n0 + wn * 32 + nt * 8 + (lane & 3) * 2;
            if (gr0 < M)
                *(float2*)(C + (size_t)gr0 * N + gc) = make_float2(acc[mt][nt][0], acc[mt][nt][1]);
            if (gr1 < M)
                *(float2*)(C + (size_t)gr1 * N + gc) = make_float2(acc[mt][nt][2], acc[mt][nt][3]);
        }
    }
}

// ---------------- per-node attention logits ----------------
__global__ void alpha_kernel(const float* __restrict__ feat,
                             const float* __restrict__ a_src,
                             const float* __restrict__ a_dst,
                             float* __restrict__ as_, float* __restrict__ ad_,
                             int Nn, int H, int C) {
    int warp = (blockIdx.x * blockDim.x + threadIdx.x) >> 5;
    int lane = threadIdx.x & 31;
    if (warp >= Nn * H) return;
    int n = warp / H, h = warp - n * H;
    const float* f = feat + (size_t)n * H * C + h * C;
    const float* s = a_src + h * C;
    const float* d = a_dst + h * C;
    float ss = 0.f, dd = 0.f;
    for (int c = lane; c < C; c += 32) {
        float v = f[c];
        ss = fmaf(v, s[c], ss);
        dd = fmaf(v, d[c], dd);
    }
#pragma unroll
    for (int o = 16; o; o >>= 1) {
        ss += __shfl_down_sync(0xffffffffu, ss, o);
        dd += __shfl_down_sync(0xffffffffu, dd, o);
    }
    if (lane == 0) { as_[warp] = ss; ad_[warp] = dd; }
}

// ---------------- GAT segment-softmax + aggregate (+ fused bf16 split out) ---
__global__ void gat_aggregate(const float* __restrict__ feat,
                              const float* __restrict__ as_,
                              const float* __restrict__ ad_,
                              const float* __restrict__ bias,
                              float* __restrict__ out,            // nullable
                              __nv_bfloat16* __restrict__ ohi,    // nullable
                              __nv_bfloat16* __restrict__ olo,
                              int H, int C, int prelu,
                              const float* __restrict__ prelu_a) {
    int n = blockIdx.x;
    int t = threadIdx.x;
    int HC = H * C;
    int h = t / C;
    extern __shared__ float sh[];
    float* smx = sh;
    float* sdn = sh + H;
    int s0 = g_rp[n], s1 = g_rp[n + 1];

    int warp = t >> 5, lane = t & 31;
    if (warp < H) {
        float ad = ad_[(size_t)n * H + warp];
        float m = -INFINITY;
        for (int k = s0 + lane; k < s1; k += 32) {
            float e = as_[(size_t)g_srcs[k] * H + warp] + ad;
            e = e > 0.f ? e : 0.2f * e;
            m = fmaxf(m, e);
        }
#pragma unroll
        for (int o = 16; o; o >>= 1) m = fmaxf(m, __shfl_xor_sync(0xffffffffu, m, o));
        float dsum = 0.f;
        for (int k = s0 + lane; k < s1; k += 32) {
            float e = as_[(size_t)g_srcs[k] * H + warp] + ad;
            e = e > 0.f ? e : 0.2f * e;
            dsum += __expf(e - m);
        }
#pragma unroll
        for (int o = 16; o; o >>= 1) dsum += __shfl_xor_sync(0xffffffffu, dsum, o);
        if (lane == 0) { smx[warp] = m; sdn[warp] = dsum + 1e-16f; }
    }
    __syncthreads();

    float m  = smx[h];
    float dn = sdn[h];
    float ad = ad_[(size_t)n * H + h];
    float acc = 0.f;
    for (int k = s0; k < s1; k++) {
        int s = g_srcs[k];
        float e = as_[(size_t)s * H + h] + ad;
        e = e > 0.f ? e : 0.2f * e;
        float w = __expf(e - m) / dn;
        acc = fmaf(feat[(size_t)s * HC + t], w, acc);
    }
    float v = acc + bias[t];
    if (prelu) { float a = prelu_a[0]; v = v >= 0.f ? v : a * v; }
    size_t idx = (size_t)n * HC + t;
    if (out) out[idx] = v;
    if (ohi) {
        __nv_bfloat16 hh = __float2bfloat16(v);
        ohi[idx] = hh;
        olo[idx] = __float2bfloat16(v - __bfloat162float(hh));
    }
}

// ---------------- host orchestration ----------------
static inline int ceil_div(int a, int b) { return (a + b - 1) / b; }

static void run_gemm(const __nv_bfloat16* Ahi, const __nv_bfloat16* Alo,
                     const __nv_bfloat16* Bhi, const __nv_bfloat16* Blo,
                     float* C, int M, int K, int N) {
    dim3 grid(N / 64, ceil_div(M, 128));
    mma_gemm<<<grid, 256>>>(Ahi, Alo, Bhi, Blo, C, M, K, N);
}

extern "C" void kernel_launch(void* const* d_in, const int* in_sizes, int n_in,
                              void* d_out, int out_size) {
    const float* x       = (const float*)d_in[0];
    const void*  eidx    = d_in[1];
    const float* W1      = (const float*)d_in[2];
    const float* a_src1  = (const float*)d_in[3];
    const float* a_dst1  = (const float*)d_in[4];
    const float* b1      = (const float*)d_in[5];
    const float* prelu_a = (const float*)d_in[6];
    const float* W2      = (const float*)d_in[7];
    const float* a_src2  = (const float*)d_in[8];
    const float* a_dst2  = (const float*)d_in[9];
    const float* b2      = (const float*)d_in[10];
    const float* Wd      = (const float*)d_in[11];
    const float* a_srcd  = (const float*)d_in[12];
    const float* a_dstd  = (const float*)d_in[13];
    const float* bd      = (const float*)d_in[14];

    const int HHc = in_sizes[3];          // 512
    const int H1  = 4;
    const int C1  = HHc / H1;             // 128
    const int M   = in_sizes[8];          // 256
    const int D   = in_sizes[12];         // 256
    const int N   = in_sizes[0] / D;      // 50000
    const int E   = in_sizes[1] / 2;      // 400000
    const int ET  = E + N;

    float* out   = (float*)d_out;
    float* z     = out;
    float* x_hat = out + (size_t)N * M;

    float *h1, *h2, *hd;
    float *as1, *ad1, *as2, *ad2, *asd, *add;
    __nv_bfloat16 *ahi, *alo, *wthi, *wtlo;
    int *cnt_p;
    cudaGetSymbolAddress((void**)&h1,  g_h1);
    cudaGetSymbolAddress((void**)&h2,  g_h2);
    cudaGetSymbolAddress((void**)&hd,  g_hd);
    cudaGetSymbolAddress((void**)&ahi, g_ahi);
    cudaGetSymbolAddress((void**)&alo, g_alo);
    cudaGetSymbolAddress((void**)&wthi, g_wthi);
    cudaGetSymbolAddress((void**)&wtlo, g_wtlo);
    cudaGetSymbolAddress((void**)&as1, g_as1);
    cudaGetSymbolAddress((void**)&ad1, g_ad1);
    cudaGetSymbolAddress((void**)&as2, g_as2);
    cudaGetSymbolAddress((void**)&ad2, g_ad2);
    cudaGetSymbolAddress((void**)&asd, g_asd);
    cudaGetSymbolAddress((void**)&add, g_add);
    cudaGetSymbolAddress((void**)&cnt_p, g_cnt);

    // ---- build CSR by destination ----
    detect_kernel<<<1, 32>>>((const int*)eidx, E);
    build_edges<<<ceil_div(ET, 256), 256>>>(eidx, E, N);
    zero_int<<<ceil_div(N, 256), 256>>>(cnt_p, N);
    hist_kernel<<<ceil_div(ET, 256), 256>>>(ET);
    scan_kernel<<<1, 1024>>>(N);
    copy_cursor<<<ceil_div(N, 256), 256>>>(N);
    scatter_kernel<<<ceil_div(ET, 256), 256>>>(ET);

    // ---- layer 1: h1 = x @ W1 ----
    split_kernel<<<ceil_div(N * D, 256), 256>>>(x, ahi, alo, N * D);
    wtsplit_kernel<<<ceil_div(D * HHc, 256), 256>>>(W1, wthi, wtlo, D, HHc);
    run_gemm(ahi, alo, wthi, wtlo, h1, N, D, HHc);
    alpha_kernel<<<ceil_div(N * H1 * 32, 256), 256>>>(h1, a_src1, a_dst1, as1, ad1, N, H1, C1);
    gat_aggregate<<<N, HHc, 2 * H1 * sizeof(float)>>>(h1, as1, ad1, b1,
                                                      nullptr, ahi, alo, H1, C1, 1, prelu_a);

    // ---- layer 2: h2 = hp @ W2 ----
    wtsplit_kernel<<<ceil_div(HHc * M, 256), 256>>>(W2, wthi, wtlo, HHc, M);
    run_gemm(ahi, alo, wthi, wtlo, h2, N, HHc, M);
    alpha_kernel<<<ceil_div(N * 32, 256), 256>>>(h2, a_src2, a_dst2, as2, ad2, N, 1, M);
    gat_aggregate<<<N, M, 2 * sizeof(float)>>>(h2, as2, ad2, b2,
                                               z, ahi, alo, 1, M, 0, prelu_a);

    // ---- decoder: hd = z @ Wd ----
    wtsplit_kernel<<<ceil_div(M * D, 256), 256>>>(Wd, wthi, wtlo, M, D);
    run_gemm(ahi, alo, wthi, wtlo, hd, N, M, D);
    alpha_kernel<<<ceil_div(N * 32, 256), 256>>>(hd, a_srcd, a_dstd, asd, add, N, 1, D);
    gat_aggregate<<<N, D, 2 * sizeof(float)>>>(hd, asd, add, bd,
                                               x_hat, nullptr, nullptr, 1, D, 0, prelu_a);
}

// round 6
// speedup vs baseline: 1.8089x; 1.4586x over previous
#include <cuda_runtime.h>
#include <cuda_bf16.h>
#include <math.h>
#include <stdint.h>

// ---------------- problem-size maxima ----------------
#define MAXN   50000
#define MAXE   400000
#define MAXET  (MAXE + MAXN)
#define MAXHC  512
#define MAXM   256

// ---------------- device scratch ----------------
__device__ int   g_src [MAXET];
__device__ int   g_dst [MAXET];
__device__ int   g_srcs[MAXET];
__device__ int   g_cnt [MAXN];
__device__ int   g_rp  [MAXN + 1];
__device__ int   g_cur [MAXN];
__device__ int   g_is64;

__device__ float g_h1 [(size_t)MAXN * MAXHC];   // GEMM outputs (fp32)
__device__ float g_h2 [(size_t)MAXN * MAXM];
__device__ float g_hd [(size_t)MAXN * MAXM];
__device__ __nv_bfloat16 g_ahi[(size_t)MAXN * MAXHC];  // split A operand
__device__ __nv_bfloat16 g_alo[(size_t)MAXN * MAXHC];
__device__ __nv_bfloat16 g_wthi[512 * 512];            // split W^T operand
__device__ __nv_bfloat16 g_wtlo[512 * 512];
__device__ float g_as1[(size_t)MAXN * 4], g_ad1[(size_t)MAXN * 4];
__device__ float g_as2[MAXN], g_ad2[MAXN];
__device__ float g_asd[MAXN], g_add[MAXN];

// ---------------- PTX helpers ----------------
__device__ __forceinline__ uint32_t smem_u32(const void* p) {
    uint32_t a;
    asm("{ .reg .u64 t; cvta.to.shared.u64 t, %1; cvt.u32.u64 %0, t; }" : "=r"(a) : "l"(p));
    return a;
}
__device__ __forceinline__ void ldmx4(uint32_t* r, uint32_t addr) {
    asm volatile("ldmatrix.sync.aligned.m8n8.x4.shared.b16 {%0,%1,%2,%3}, [%4];"
        : "=r"(r[0]), "=r"(r[1]), "=r"(r[2]), "=r"(r[3]) : "r"(addr));
}
__device__ __forceinline__ void mma16816(float* c, const uint32_t* a,
                                         uint32_t b0, uint32_t b1) {
    asm volatile(
        "mma.sync.aligned.m16n8k16.row.col.f32.bf16.bf16.f32 "
        "{%0,%1,%2,%3}, {%4,%5,%6,%7}, {%8,%9}, {%0,%1,%2,%3};"
        : "+f"(c[0]), "+f"(c[1]), "+f"(c[2]), "+f"(c[3])
        : "r"(a[0]), "r"(a[1]), "r"(a[2]), "r"(a[3]), "r"(b0), "r"(b1));
}

// ---------------- graph-building kernels ----------------
__global__ void detect_kernel(const int* __restrict__ ei32, int E) {
    if (threadIdx.x == 0 && blockIdx.x == 0) {
        int nz = 0;
        int cnt = E < 64 ? E : 64;
        for (int i = 0; i < cnt; i++) nz |= ei32[2 * i + 1];
        g_is64 = (nz == 0) ? 1 : 0;
    }
}
__global__ void build_edges(const void* __restrict__ ei, int E, int Nn) {
    int i = blockIdx.x * blockDim.x + threadIdx.x;
    int tot = E + Nn;
    if (i >= tot) return;
    int s, d;
    if (i < E) {
        if (g_is64) {
            const long long* p = (const long long*)ei;
            s = (int)p[i]; d = (int)p[E + i];
        } else {
            const int* p = (const int*)ei;
            s = p[i]; d = p[E + i];
        }
    } else { s = d = i - E; }
    g_src[i] = s; g_dst[i] = d;
}
__global__ void zero_int(int* p, int n) {
    int i = blockIdx.x * blockDim.x + threadIdx.x;
    if (i < n) p[i] = 0;
}
__global__ void hist_kernel(int tot) {
    int i = blockIdx.x * blockDim.x + threadIdx.x;
    if (i < tot) atomicAdd(&g_cnt[g_dst[i]], 1);
}
__global__ void scan_kernel(int n) {
    __shared__ int sh[1024];
    __shared__ int carry;
    if (threadIdx.x == 0) carry = 0;
    __syncthreads();
    for (int base = 0; base < n; base += 1024) {
        int i = base + threadIdx.x;
        int v = (i < n) ? g_cnt[i] : 0;
        sh[threadIdx.x] = v;
        __syncthreads();
        for (int off = 1; off < 1024; off <<= 1) {
            int t = (threadIdx.x >= off) ? sh[threadIdx.x - off] : 0;
            __syncthreads();
            sh[threadIdx.x] += t;
            __syncthreads();
        }
        if (i < n) g_rp[i + 1] = sh[threadIdx.x] + carry;
        __syncthreads();
        if (threadIdx.x == 0) carry += sh[1023];
        __syncthreads();
    }
    if (threadIdx.x == 0) g_rp[0] = 0;
}
__global__ void copy_cursor(int n) {
    int i = blockIdx.x * blockDim.x + threadIdx.x;
    if (i < n) g_cur[i] = g_rp[i];
}
__global__ void scatter_kernel(int tot) {
    int i = blockIdx.x * blockDim.x + threadIdx.x;
    if (i >= tot) return;
    int d = g_dst[i];
    int pos = atomicAdd(&g_cur[d], 1);
    g_srcs[pos] = g_src[i];
}

// ---------------- bf16 split conversions ----------------
__global__ void split_kernel(const float* __restrict__ src,
                             __nv_bfloat16* __restrict__ hi,
                             __nv_bfloat16* __restrict__ lo, int total) {
    int i = blockIdx.x * blockDim.x + threadIdx.x;
    if (i >= total) return;
    float v = src[i];
    __nv_bfloat16 h = __float2bfloat16(v);
    hi[i] = h;
    lo[i] = __float2bfloat16(v - __bfloat162float(h));
}
// W[K,N] -> Wt_hi/lo[N,K]
__global__ void wtsplit_kernel(const float* __restrict__ W,
                               __nv_bfloat16* __restrict__ hi,
                               __nv_bfloat16* __restrict__ lo, int K, int N) {
    int idx = blockIdx.x * blockDim.x + threadIdx.x;
    if (idx >= K * N) return;
    int k = idx / N, n = idx - k * N;
    float v = W[idx];
    __nv_bfloat16 h = __float2bfloat16(v);
    hi[(size_t)n * K + k] = h;
    lo[(size_t)n * K + k] = __float2bfloat16(v - __bfloat162float(h));
}

// ---------------- split-bf16 tensor-core GEMM (mma.sync / HMMA) --------------
// C[M,N] = Ahi/lo[M,K] @ (Bt hi/lo[N,K])^T, fp32 accumulate.
// CTA tile 128x64, BK=32, 8 warps (4M x 2N), warp tile 32x32.
__global__ void __launch_bounds__(256, 2)
mma_gemm(const __nv_bfloat16* __restrict__ Ahi, const __nv_bfloat16* __restrict__ Alo,
         const __nv_bfloat16* __restrict__ Bhi, const __nv_bfloat16* __restrict__ Blo,
         float* __restrict__ C, int M, int K, int N) {
    __shared__ __align__(16) uint8_t sAh[128 * 80], sAl[128 * 80];
    __shared__ __align__(16) uint8_t sBh[64 * 80],  sBl[64 * 80];
    int tid = threadIdx.x, lane = tid & 31, wid = tid >> 5;
    int wm = wid & 3, wn = wid >> 2;
    int m0 = blockIdx.y * 128, n0 = blockIdx.x * 64;

    int lr = tid >> 2, lc = tid & 3;
    int gm0 = m0 + lr, gm1 = m0 + lr + 64;
    const size_t a0off = (size_t)gm0 * K + lc * 8;
    const size_t a1off = (size_t)gm1 * K + lc * 8;
    const size_t bOff  = (size_t)(n0 + lr) * K + lc * 8;
    uint32_t stA0 = (uint32_t)(lr * 80 + lc * 16);
    uint32_t stA1 = (uint32_t)((lr + 64) * 80 + lc * 16);

    uint32_t sAhB = smem_u32(sAh), sAlB = smem_u32(sAl);
    uint32_t sBhB = smem_u32(sBh), sBlB = smem_u32(sBl);

    uint32_t aoffs[2], boffs[2];
#pragma unroll
    for (int mt = 0; mt < 2; mt++)
        aoffs[mt] = (uint32_t)((wm * 32 + mt * 16 + (lane & 15)) * 80 + (lane >> 4) * 16);
#pragma unroll
    for (int p = 0; p < 2; p++)
        boffs[p] = (uint32_t)((wn * 32 + p * 16 + ((lane >> 3) & 1) * 8 + (lane & 7)) * 80
                              + (lane >> 4) * 16);

    float acc[2][4][4];
#pragma unroll
    for (int i = 0; i < 2; i++)
#pragma unroll
        for (int j = 0; j < 4; j++)
#pragma unroll
            for (int q = 0; q < 4; q++) acc[i][j][q] = 0.f;

    const uint4 z4 = make_uint4(0, 0, 0, 0);
    uint4 pa0h, pa1h, pa0l, pa1l, pbh, pbl;
    pa0h = (gm0 < M) ? *(const uint4*)(Ahi + a0off) : z4;
    pa1h = (gm1 < M) ? *(const uint4*)(Ahi + a1off) : z4;
    pa0l = (gm0 < M) ? *(const uint4*)(Alo + a0off) : z4;
    pa1l = (gm1 < M) ? *(const uint4*)(Alo + a1off) : z4;
    pbh  = *(const uint4*)(Bhi + bOff);
    pbl  = *(const uint4*)(Blo + bOff);

    int nch = K >> 5;
    for (int ch = 0; ch < nch; ch++) {
        *(uint4*)(sAh + stA0) = pa0h;
        *(uint4*)(sAh + stA1) = pa1h;
        *(uint4*)(sAl + stA0) = pa0l;
        *(uint4*)(sAl + stA1) = pa1l;
        *(uint4*)(sBh + stA0) = pbh;
        *(uint4*)(sBl + stA0) = pbl;
        __syncthreads();

        if (ch + 1 < nch) {
            int k8 = (ch + 1) * 32;
            pa0h = (gm0 < M) ? *(const uint4*)(Ahi + a0off + k8) : z4;
            pa1h = (gm1 < M) ? *(const uint4*)(Ahi + a1off + k8) : z4;
            pa0l = (gm0 < M) ? *(const uint4*)(Alo + a0off + k8) : z4;
            pa1l = (gm1 < M) ? *(const uint4*)(Alo + a1off + k8) : z4;
            pbh  = *(const uint4*)(Bhi + bOff + k8);
            pbl  = *(const uint4*)(Blo + bOff + k8);
        }

#pragma unroll
        for (int ks = 0; ks < 2; ks++) {
            uint32_t AH[2][4], AL[2][4], BH[2][4], BL[2][4];
            ldmx4(AH[0], sAhB + aoffs[0] + ks * 32);
            ldmx4(AH[1], sAhB + aoffs[1] + ks * 32);
            ldmx4(AL[0], sAlB + aoffs[0] + ks * 32);
            ldmx4(AL[1], sAlB + aoffs[1] + ks * 32);
            ldmx4(BH[0], sBhB + boffs[0] + ks * 32);
            ldmx4(BH[1], sBhB + boffs[1] + ks * 32);
            ldmx4(BL[0], sBlB + boffs[0] + ks * 32);
            ldmx4(BL[1], sBlB + boffs[1] + ks * 32);
#pragma unroll
            for (int mt = 0; mt < 2; mt++) {
#pragma unroll
                for (int p = 0; p < 2; p++) {
                    mma16816(acc[mt][p * 2 + 0], AH[mt], BH[p][0], BH[p][2]);
                    mma16816(acc[mt][p * 2 + 1], AH[mt], BH[p][1], BH[p][3]);
                    mma16816(acc[mt][p * 2 + 0], AH[mt], BL[p][0], BL[p][2]);
                    mma16816(acc[mt][p * 2 + 1], AH[mt], BL[p][1], BL[p][3]);
                    mma16816(acc[mt][p * 2 + 0], AL[mt], BH[p][0], BH[p][2]);
                    mma16816(acc[mt][p * 2 + 1], AL[mt], BH[p][1], BH[p][3]);
                }
            }
        }
        __syncthreads();
    }

#pragma unroll
    for (int mt = 0; mt < 2; mt++) {
        int gr0 = m0 + wm * 32 + mt * 16 + (lane >> 2);
        int gr1 = gr0 + 8;
#pragma unroll
        for (int nt = 0; nt < 4; nt++) {
            int gc = n0 + wn * 32 + nt * 8 + (lane & 3) * 2;
            if (gr0 < M)
                *(float2*)(C + (size_t)gr0 * N + gc) = make_float2(acc[mt][nt][0], acc[mt][nt][1]);
            if (gr1 < M)
                *(float2*)(C + (size_t)gr1 * N + gc) = make_float2(acc[mt][nt][2], acc[mt][nt][3]);
        }
    }
}

// ---------------- per-node attention logits ----------------
__global__ void alpha_kernel(const float* __restrict__ feat,
                             const float* __restrict__ a_src,
                             const float* __restrict__ a_dst,
                             float* __restrict__ as_, float* __restrict__ ad_,
                             int Nn, int H, int C) {
    int warp = (blockIdx.x * blockDim.x + threadIdx.x) >> 5;
    int lane = threadIdx.x & 31;
    if (warp >= Nn * H) return;
    int n = warp / H, h = warp - n * H;
    const float* f = feat + (size_t)n * H * C + h * C;
    const float* s = a_src + h * C;
    const float* d = a_dst + h * C;
    float ss = 0.f, dd = 0.f;
    for (int c = lane; c < C; c += 32) {
        float v = f[c];
        ss = fmaf(v, s[c], ss);
        dd = fmaf(v, d[c], dd);
    }
#pragma unroll
    for (int o = 16; o; o >>= 1) {
        ss += __shfl_down_sync(0xffffffffu, ss, o);
        dd += __shfl_down_sync(0xffffffffu, dd, o);
    }
    if (lane == 0) { as_[warp] = ss; ad_[warp] = dd; }
}

// ---------------- GAT segment-softmax + aggregate ----------------
// Weights computed ONCE per (node, edge, head) into smem; accumulate loop is
// pure LDS-broadcast + coalesced gather + FFMA (no exp/div in hot path).
#define CHUNK 64
__global__ void gat_aggregate(const float* __restrict__ feat,
                              const float* __restrict__ as_,
                              const float* __restrict__ ad_,
                              const float* __restrict__ bias,
                              float* __restrict__ out,            // nullable
                              __nv_bfloat16* __restrict__ ohi,    // nullable
                              __nv_bfloat16* __restrict__ olo,
                              int H, int C, int prelu,
                              const float* __restrict__ prelu_a) {
    int n = blockIdx.x;
    int t = threadIdx.x;
    int HC = H * C;
    int h = t / C;
    __shared__ float sw[4 * CHUNK];
    __shared__ int   ssrc[CHUNK];
    int s0 = g_rp[n], s1 = g_rp[n + 1];
    int warp = t >> 5, lane = t & 31;

    // phase 1: softmax stats, kept in registers of the head-warps
    float m = 0.f, rdn = 0.f, ad = 0.f;
    if (warp < H) {
        ad = ad_[(size_t)n * H + warp];
        m = -INFINITY;
        for (int k = s0 + lane; k < s1; k += 32) {
            float e = as_[(size_t)g_srcs[k] * H + warp] + ad;
            e = e > 0.f ? e : 0.2f * e;
            m = fmaxf(m, e);
        }
#pragma unroll
        for (int o = 16; o; o >>= 1) m = fmaxf(m, __shfl_xor_sync(0xffffffffu, m, o));
        float ds = 0.f;
        for (int k = s0 + lane; k < s1; k += 32) {
            float e = as_[(size_t)g_srcs[k] * H + warp] + ad;
            e = e > 0.f ? e : 0.2f * e;
            ds += __expf(e - m);
        }
#pragma unroll
        for (int o = 16; o; o >>= 1) ds += __shfl_xor_sync(0xffffffffu, ds, o);
        rdn = 1.f / (ds + 1e-16f);
    }

    // phase 2: chunked weight materialization + aggregation
    float acc = 0.f;
    for (int base = s0; base < s1; base += CHUNK) {
        int count = min(CHUNK, s1 - base);
        __syncthreads();
        if (warp < H) {
            for (int j = lane; j < count; j += 32) {
                int s = g_srcs[base + j];
                if (warp == 0) ssrc[j] = s;
                float e = as_[(size_t)s * H + warp] + ad;
                e = e > 0.f ? e : 0.2f * e;
                sw[warp * CHUNK + j] = __expf(e - m) * rdn;
            }
        }
        __syncthreads();
        const float* swh = sw + h * CHUNK;
        for (int j = 0; j < count; j++) {
            acc = fmaf(feat[(size_t)ssrc[j] * HC + t], swh[j], acc);
        }
    }

    float v = acc + bias[t];
    if (prelu) { float a = prelu_a[0]; v = v >= 0.f ? v : a * v; }
    size_t idx = (size_t)n * HC + t;
    if (out) out[idx] = v;
    if (ohi) {
        __nv_bfloat16 hh = __float2bfloat16(v);
        ohi[idx] = hh;
        olo[idx] = __float2bfloat16(v - __bfloat162float(hh));
    }
}

// ---------------- host orchestration ----------------
static inline int ceil_div(int a, int b) { return (a + b - 1) / b; }

static void run_gemm(const __nv_bfloat16* Ahi, const __nv_bfloat16* Alo,
                     const __nv_bfloat16* Bhi, const __nv_bfloat16* Blo,
                     float* C, int M, int K, int N) {
    dim3 grid(N / 64, ceil_div(M, 128));
    mma_gemm<<<grid, 256>>>(Ahi, Alo, Bhi, Blo, C, M, K, N);
}

extern "C" void kernel_launch(void* const* d_in, const int* in_sizes, int n_in,
                              void* d_out, int out_size) {
    const float* x       = (const float*)d_in[0];
    const void*  eidx    = d_in[1];
    const float* W1      = (const float*)d_in[2];
    const float* a_src1  = (const float*)d_in[3];
    const float* a_dst1  = (const float*)d_in[4];
    const float* b1      = (const float*)d_in[5];
    const float* prelu_a = (const float*)d_in[6];
    const float* W2      = (const float*)d_in[7];
    const float* a_src2  = (const float*)d_in[8];
    const float* a_dst2  = (const float*)d_in[9];
    const float* b2      = (const float*)d_in[10];
    const float* Wd      = (const float*)d_in[11];
    const float* a_srcd  = (const float*)d_in[12];
    const float* a_dstd  = (const float*)d_in[13];
    const float* bd      = (const float*)d_in[14];

    const int HHc = in_sizes[3];          // 512
    const int H1  = 4;
    const int C1  = HHc / H1;             // 128
    const int M   = in_sizes[8];          // 256
    const int D   = in_sizes[12];         // 256
    const int N   = in_sizes[0] / D;      // 50000
    const int E   = in_sizes[1] / 2;      // 400000
    const int ET  = E + N;

    float* out   = (float*)d_out;
    float* z     = out;
    float* x_hat = out + (size_t)N * M;

    float *h1, *h2, *hd;
    float *as1, *ad1, *as2, *ad2, *asd, *add;
    __nv_bfloat16 *ahi, *alo, *wthi, *wtlo;
    int *cnt_p;
    cudaGetSymbolAddress((void**)&h1,  g_h1);
    cudaGetSymbolAddress((void**)&h2,  g_h2);
    cudaGetSymbolAddress((void**)&hd,  g_hd);
    cudaGetSymbolAddress((void**)&ahi, g_ahi);
    cudaGetSymbolAddress((void**)&alo, g_alo);
    cudaGetSymbolAddress((void**)&wthi, g_wthi);
    cudaGetSymbolAddress((void**)&wtlo, g_wtlo);
    cudaGetSymbolAddress((void**)&as1, g_as1);
    cudaGetSymbolAddress((void**)&ad1, g_ad1);
    cudaGetSymbolAddress((void**)&as2, g_as2);
    cudaGetSymbolAddress((void**)&ad2, g_ad2);
    cudaGetSymbolAddress((void**)&asd, g_asd);
    cudaGetSymbolAddress((void**)&add, g_add);
    cudaGetSymbolAddress((void**)&cnt_p, g_cnt);

    // ---- build CSR by destination ----
    detect_kernel<<<1, 32>>>((const int*)eidx, E);
    build_edges<<<ceil_div(ET, 256), 256>>>(eidx, E, N);
    zero_int<<<ceil_div(N, 256), 256>>>(cnt_p, N);
    hist_kernel<<<ceil_div(ET, 256), 256>>>(ET);
    scan_kernel<<<1, 1024>>>(N);
    copy_cursor<<<ceil_div(N, 256), 256>>>(N);
    scatter_kernel<<<ceil_div(ET, 256), 256>>>(ET);

    // ---- layer 1: h1 = x @ W1 ----
    split_kernel<<<ceil_div(N * D, 256), 256>>>(x, ahi, alo, N * D);
    wtsplit_kernel<<<ceil_div(D * HHc, 256), 256>>>(W1, wthi, wtlo, D, HHc);
    run_gemm(ahi, alo, wthi, wtlo, h1, N, D, HHc);
    alpha_kernel<<<ceil_div(N * H1 * 32, 256), 256>>>(h1, a_src1, a_dst1, as1, ad1, N, H1, C1);
    gat_aggregate<<<N, HHc>>>(h1, as1, ad1, b1, nullptr, ahi, alo, H1, C1, 1, prelu_a);

    // ---- layer 2: h2 = hp @ W2 ----
    wtsplit_kernel<<<ceil_div(HHc * M, 256), 256>>>(W2, wthi, wtlo, HHc, M);
    run_gemm(ahi, alo, wthi, wtlo, h2, N, HHc, M);
    alpha_kernel<<<ceil_div(N * 32, 256), 256>>>(h2, a_src2, a_dst2, as2, ad2, N, 1, M);
    gat_aggregate<<<N, M>>>(h2, as2, ad2, b2, z, ahi, alo, 1, M, 0, prelu_a);

    // ---- decoder: hd = z @ Wd ----
    wtsplit_kernel<<<ceil_div(M * D, 256), 256>>>(Wd, wthi, wtlo, M, D);
    run_gemm(ahi, alo, wthi, wtlo, hd, N, M, D);
    alpha_kernel<<<ceil_div(N * 32, 256), 256>>>(hd, a_srcd, a_dstd, asd, add, N, 1, D);
    gat_aggregate<<<N, D>>>(hd, asd, add, bd, x_hat, nullptr, nullptr, 1, D, 0, prelu_a);
}